// round 1
// baseline (speedup 1.0000x reference)
#include <cuda_runtime.h>

// SelfAttentionHead: out = softmax(causal(QK^T / sqrt(dk))) V
// Q/K/V = x @ W_{q,k,v};  B=16, T=2048, DM=1024, DK=128, fp32.

#define NB 16
#define T 2048
#define DM 1024
#define DK 128
#define BT (NB * T)

#define BM 64
#define BN 64
#define QP 132   // pitch (floats) for Qs/Ks rows: 132 ≡ 4 mod 32 banks -> spreads row-strided reads
#define VP 128   // Vs accessed row-wise contiguously -> no pad needed
#define SP 68    // Ss pitch

// Scratch for projected Q, K, V (allocation-free rule: __device__ globals)
__device__ float g_qkv[3][(size_t)BT * DK];

// ---------------------------------------------------------------------------
// QKV projection: out[sel] = x @ W_sel.  M=BT(32768), K=DM(1024), N=DK(128)
// grid (BT/64, 3), 256 threads. Block tile 64x128, thread micro-tile 8x4.
// ---------------------------------------------------------------------------
__global__ void __launch_bounds__(256) qkv_gemm_kernel(
    const float* __restrict__ x, const float* __restrict__ Wq,
    const float* __restrict__ Wk, const float* __restrict__ Wv)
{
    __shared__ float As[64][16];
    __shared__ float Bs[16][128];

    const float* W = (blockIdx.y == 0) ? Wq : (blockIdx.y == 1 ? Wk : Wv);
    float* outp = g_qkv[blockIdx.y];

    const int t  = threadIdx.x;
    const int m0 = blockIdx.x * 64;

    // A tile loads: row = t/4, col4 = (t%4)*4   (64x16 = 256 float4)
    const int ar = t >> 2, ac = (t & 3) << 2;
    // B tile loads: 2 float4/thread: rows t/32 and t/32+8, col4 = (t%32)*4
    const int br = t >> 5, bc = (t & 31) << 2;
    // compute mapping: rows rg*8..+7, cols cg*4..+3
    const int rg = t >> 5, cg = t & 31;

    const float* xp = x + (size_t)(m0 + ar) * DM + ac;
    const float* wp = W + (size_t)br * DK + bc;

    float acc[8][4];
    #pragma unroll
    for (int i = 0; i < 8; i++)
        #pragma unroll
        for (int j = 0; j < 4; j++) acc[i][j] = 0.0f;

    // software pipeline: preload chunk 0
    float4 a  = *(const float4*)(xp);
    float4 b0 = *(const float4*)(wp);
    float4 b1 = *(const float4*)(wp + 8 * DK);

    for (int k0 = 0; k0 < DM; k0 += 16) {
        __syncthreads();
        *(float4*)&As[ar][ac]      = a;
        *(float4*)&Bs[br][bc]      = b0;
        *(float4*)&Bs[br + 8][bc]  = b1;
        __syncthreads();

        if (k0 + 16 < DM) {   // prefetch next chunk while computing this one
            a  = *(const float4*)(xp + k0 + 16);
            b0 = *(const float4*)(wp + (size_t)(k0 + 16) * DK);
            b1 = *(const float4*)(wp + (size_t)(k0 + 24) * DK);
        }

        #pragma unroll
        for (int kk = 0; kk < 16; kk++) {
            float4 bb = *(const float4*)&Bs[kk][cg << 2];   // conflict-free
            #pragma unroll
            for (int i = 0; i < 8; i++) {
                float aa = As[(rg << 3) + i][kk];           // warp broadcast
                acc[i][0] += aa * bb.x;
                acc[i][1] += aa * bb.y;
                acc[i][2] += aa * bb.z;
                acc[i][3] += aa * bb.w;
            }
        }
    }

    float* op = outp + (size_t)(m0 + (rg << 3)) * DK + (cg << 2);
    #pragma unroll
    for (int i = 0; i < 8; i++) {
        float4 v = make_float4(acc[i][0], acc[i][1], acc[i][2], acc[i][3]);
        *(float4*)(op + (size_t)i * DK) = v;
    }
}

// ---------------------------------------------------------------------------
// Flash attention (causal, online softmax).
// grid (T/BM, B), 256 threads, dynamic smem.
// Thread layout: ty = t/16 (row group), tx = t%16.
//   S tile 64x64: thread computes rows ty*4+i (i<4), cols tx+16*j (j<4).
//   O tile 64x128: thread holds rows ty*4+i, cols tx*8..tx*8+7.
// ---------------------------------------------------------------------------
struct __align__(16) AttnSmem {
    float Qs[BM * QP];
    float Ks[BN * QP];
    float Vs[BN * VP];
    float Ss[BM * SP];
    float mrow[BM];
    float lrow[BM];
    float crow[BM];
};

extern __shared__ char attn_smem_raw[];

__global__ void __launch_bounds__(256) attn_kernel(float* __restrict__ out)
{
    AttnSmem& sm = *reinterpret_cast<AttnSmem*>(attn_smem_raw);
    const int t  = threadIdx.x;
    const int b  = blockIdx.y;
    // reverse so the longest (largest-qb) CTAs launch first (wave balance)
    const int qb = (int)(gridDim.x - 1) - (int)blockIdx.x;
    const int q0 = qb * BM;

    const float* Q = g_qkv[0] + (size_t)b * T * DK;
    const float* K = g_qkv[1] + (size_t)b * T * DK;
    const float* V = g_qkv[2] + (size_t)b * T * DK;

    // Load Q tile (64x128): 8 float4 per thread, coalesced
    #pragma unroll
    for (int i = 0; i < 8; i++) {
        int f = t + 256 * i;
        int r = f >> 5, c = (f & 31) << 2;
        *(float4*)&sm.Qs[r * QP + c] = *(const float4*)(Q + (size_t)(q0 + r) * DK + c);
    }
    if (t < BM) { sm.mrow[t] = -1e30f; sm.lrow[t] = 0.0f; }

    const int ty = t >> 4, tx = t & 15;
    const int r0 = ty << 2;

    float o[4][8];
    #pragma unroll
    for (int i = 0; i < 4; i++)
        #pragma unroll
        for (int j = 0; j < 8; j++) o[i][j] = 0.0f;

    const float scale = 0.08838834764831845f;  // 1/sqrt(128)

    for (int kb = 0; kb <= qb; kb++) {
        const int k0 = kb * BN;

        __syncthreads();  // previous iteration done with Ks/Vs/Ss
        #pragma unroll
        for (int i = 0; i < 8; i++) {
            int f = t + 256 * i;
            int r = f >> 5, c = (f & 31) << 2;
            *(float4*)&sm.Ks[r * QP + c] = *(const float4*)(K + (size_t)(k0 + r) * DK + c);
            *(float4*)&sm.Vs[r * VP + c] = *(const float4*)(V + (size_t)(k0 + r) * DK + c);
        }
        __syncthreads();

        // ---- S = Q K^T (64x64 tile, 4x4 per thread) ----
        float s[4][4];
        #pragma unroll
        for (int i = 0; i < 4; i++)
            #pragma unroll
            for (int j = 0; j < 4; j++) s[i][j] = 0.0f;

        for (int k = 0; k < DK; k += 4) {
            float qa[4][4], ka[4][4];
            #pragma unroll
            for (int i = 0; i < 4; i++)
                *(float4*)qa[i] = *(const float4*)&sm.Qs[(r0 + i) * QP + k];
            #pragma unroll
            for (int j = 0; j < 4; j++)
                *(float4*)ka[j] = *(const float4*)&sm.Ks[(tx + 16 * j) * QP + k];
            #pragma unroll
            for (int i = 0; i < 4; i++)
                #pragma unroll
                for (int j = 0; j < 4; j++)
                    #pragma unroll
                    for (int d = 0; d < 4; d++)
                        s[i][j] += qa[i][d] * ka[j][d];
        }

        // ---- scale, causal mask (only the diagonal block needs masking) ----
        if (kb == qb) {
            #pragma unroll
            for (int i = 0; i < 4; i++)
                #pragma unroll
                for (int j = 0; j < 4; j++) {
                    int lq = r0 + i, lk = tx + 16 * j;
                    sm.Ss[lq * SP + lk] = (lk <= lq) ? s[i][j] * scale : -1e30f;
                }
        } else {
            #pragma unroll
            for (int i = 0; i < 4; i++)
                #pragma unroll
                for (int j = 0; j < 4; j++)
                    sm.Ss[(r0 + i) * SP + (tx + 16 * j)] = s[i][j] * scale;
        }
        __syncthreads();

        // ---- online softmax: 4 threads per row (same warp -> shfl reduce) ----
        {
            int rr = t >> 2, pp = t & 3;
            float* srow = &sm.Ss[rr * SP + (pp << 4)];
            float mx = -1e30f;
            #pragma unroll
            for (int c = 0; c < 16; c++) mx = fmaxf(mx, srow[c]);
            mx = fmaxf(mx, __shfl_xor_sync(0xffffffffu, mx, 1));
            mx = fmaxf(mx, __shfl_xor_sync(0xffffffffu, mx, 2));
            float mold = sm.mrow[rr];
            float mnew = fmaxf(mold, mx);
            float sum = 0.0f;
            #pragma unroll
            for (int c = 0; c < 16; c++) {
                float e = __expf(srow[c] - mnew);
                srow[c] = e;
                sum += e;
            }
            sum += __shfl_xor_sync(0xffffffffu, sum, 1);
            sum += __shfl_xor_sync(0xffffffffu, sum, 2);
            if (pp == 0) {
                float corr = __expf(mold - mnew);   // 0 on first live block
                sm.crow[rr] = corr;
                sm.lrow[rr] = sm.lrow[rr] * corr + sum;
                sm.mrow[rr] = mnew;
            }
        }
        __syncthreads();

        // ---- rescale O, then O += P V ----
        #pragma unroll
        for (int i = 0; i < 4; i++) {
            float c = sm.crow[r0 + i];
            #pragma unroll
            for (int j = 0; j < 8; j++) o[i][j] *= c;
        }

        for (int s0 = 0; s0 < BN; s0 += 4) {
            float pr[4][4];
            #pragma unroll
            for (int i = 0; i < 4; i++)
                *(float4*)pr[i] = *(const float4*)&sm.Ss[(r0 + i) * SP + s0];
            #pragma unroll
            for (int d = 0; d < 4; d++) {
                float4 va = *(const float4*)&sm.Vs[(s0 + d) * VP + (tx << 3)];
                float4 vb = *(const float4*)&sm.Vs[(s0 + d) * VP + (tx << 3) + 4];
                #pragma unroll
                for (int i = 0; i < 4; i++) {
                    float p = pr[i][d];
                    o[i][0] += p * va.x;  o[i][1] += p * va.y;
                    o[i][2] += p * va.z;  o[i][3] += p * va.w;
                    o[i][4] += p * vb.x;  o[i][5] += p * vb.y;
                    o[i][6] += p * vb.z;  o[i][7] += p * vb.w;
                }
            }
        }
    }

    // ---- epilogue: normalize by l and store ----
    float* op = out + ((size_t)b * T + q0) * DK + (tx << 3);
    #pragma unroll
    for (int i = 0; i < 4; i++) {
        float inv = 1.0f / sm.lrow[r0 + i];
        float4 v0 = make_float4(o[i][0] * inv, o[i][1] * inv, o[i][2] * inv, o[i][3] * inv);
        float4 v1 = make_float4(o[i][4] * inv, o[i][5] * inv, o[i][6] * inv, o[i][7] * inv);
        *(float4*)(op + (size_t)(r0 + i) * DK)     = v0;
        *(float4*)(op + (size_t)(r0 + i) * DK + 4) = v1;
    }
}

// ---------------------------------------------------------------------------
extern "C" void kernel_launch(void* const* d_in, const int* in_sizes, int n_in,
                              void* d_out, int out_size)
{
    const float* x  = (const float*)d_in[0];
    const float* Wq = (const float*)d_in[1];
    const float* Wk = (const float*)d_in[2];
    const float* Wv = (const float*)d_in[3];
    float* out = (float*)d_out;

    dim3 g1(BT / 64, 3);
    qkv_gemm_kernel<<<g1, 256>>>(x, Wq, Wk, Wv);

    int smem = (int)sizeof(AttnSmem);
    cudaFuncSetAttribute(attn_kernel, cudaFuncAttributeMaxDynamicSharedMemorySize, smem);
    dim3 g2(T / BM, NB);
    attn_kernel<<<g2, 256, (size_t)smem>>>(out);
}

// round 2
// speedup vs baseline: 2.5375x; 2.5375x over previous
#include <cuda_runtime.h>

// SelfAttentionHead via tf32 tensor-core mma.sync (m16n8k8).
// B=16, T=2048, DM=1024, DK=128, fp32 in/out.

#define NB 16
#define T 2048
#define DM 1024
#define DK 128
#define BT (NB * T)

__device__ float g_qkv[3][(size_t)BT * DK];

__device__ __forceinline__ unsigned f2tf(float f) {
    unsigned u; asm("cvt.rna.tf32.f32 %0, %1;" : "=r"(u) : "f"(f)); return u;
}
__device__ __forceinline__ float f2tff(float f) { return __uint_as_float(f2tf(f)); }

#define MMA_TF32(d, a0, a1, a2, a3, b0, b1)                                  \
    asm volatile("mma.sync.aligned.m16n8k8.row.col.f32.tf32.tf32.f32 "       \
                 "{%0,%1,%2,%3}, {%4,%5,%6,%7}, {%8,%9}, {%0,%1,%2,%3};"     \
                 : "+f"(d[0]), "+f"(d[1]), "+f"(d[2]), "+f"(d[3])            \
                 : "r"(a0), "r"(a1), "r"(a2), "r"(a3), "r"(b0), "r"(b1))

// ===========================================================================
// QKV GEMM: out[sel] = x @ W_sel.  M=32768, K=1024, N=128.
// grid (3, 256): x = qkv selector (so L2 shares x tiles across q/k/v),
// y = M-tile. 256 threads = 8 warps (4m x 2n), warp tile 32x64.
// ===========================================================================
#define KC 16
#define GAP 20    // As pitch: 20 mod 32 = 20 -> lq*20 spans all bank groups
#define GBP 136   // Bs pitch: 136 mod 32 = 8 -> lr*8 + lq conflict-free

__global__ void __launch_bounds__(256) qkv_gemm_kernel(
    const float* __restrict__ x, const float* __restrict__ Wq,
    const float* __restrict__ Wk, const float* __restrict__ Wv)
{
    __shared__ float As[128 * GAP];
    __shared__ float Bs[KC * GBP];

    const int sel = blockIdx.x;
    const float* W = (sel == 0) ? Wq : (sel == 1 ? Wk : Wv);
    float* outp = g_qkv[sel];
    const int m0 = blockIdx.y * 128;

    const int t = threadIdx.x;
    const int lane = t & 31, wid = t >> 5;
    const int wm = wid >> 1, wn = wid & 1;
    const int lq = lane >> 2, lr = lane & 3;

    const float* xp = x + (size_t)m0 * DM;

    float4 ra[2], rb[2];
    #pragma unroll
    for (int i = 0; i < 2; i++) {
        int f = t + 256 * i;
        ra[i] = *(const float4*)(xp + (size_t)(f >> 2) * DM + (f & 3) * 4);
        rb[i] = *(const float4*)(W + (size_t)(f >> 5) * DK + (f & 31) * 4);
    }

    float c[2][8][4];
    #pragma unroll
    for (int mt = 0; mt < 2; mt++)
        #pragma unroll
        for (int nt = 0; nt < 8; nt++)
            #pragma unroll
            for (int k = 0; k < 4; k++) c[mt][nt][k] = 0.0f;

    for (int k0 = 0; k0 < DM; k0 += KC) {
        __syncthreads();
        #pragma unroll
        for (int i = 0; i < 2; i++) {
            int f = t + 256 * i;
            float4 a = ra[i], bv = rb[i];
            float* ap = &As[(f >> 2) * GAP + (f & 3) * 4];
            ap[0] = f2tff(a.x); ap[1] = f2tff(a.y);
            ap[2] = f2tff(a.z); ap[3] = f2tff(a.w);
            float* bp = &Bs[(f >> 5) * GBP + (f & 31) * 4];
            bp[0] = f2tff(bv.x); bp[1] = f2tff(bv.y);
            bp[2] = f2tff(bv.z); bp[3] = f2tff(bv.w);
        }
        __syncthreads();

        if (k0 + KC < DM) {
            #pragma unroll
            for (int i = 0; i < 2; i++) {
                int f = t + 256 * i;
                ra[i] = *(const float4*)(xp + (size_t)(f >> 2) * DM + (k0 + KC) + (f & 3) * 4);
                rb[i] = *(const float4*)(W + (size_t)(k0 + KC + (f >> 5)) * DK + (f & 31) * 4);
            }
        }

        #pragma unroll
        for (int kk = 0; kk < KC; kk += 8) {
            unsigned a[2][4];
            #pragma unroll
            for (int mt = 0; mt < 2; mt++) {
                int r = wm * 32 + mt * 16 + lq;
                a[mt][0] = __float_as_uint(As[r * GAP + kk + lr]);
                a[mt][1] = __float_as_uint(As[(r + 8) * GAP + kk + lr]);
                a[mt][2] = __float_as_uint(As[r * GAP + kk + 4 + lr]);
                a[mt][3] = __float_as_uint(As[(r + 8) * GAP + kk + 4 + lr]);
            }
            #pragma unroll
            for (int nt = 0; nt < 8; nt++) {
                int col = wn * 64 + nt * 8 + lq;
                unsigned b0 = __float_as_uint(Bs[(kk + lr) * GBP + col]);
                unsigned b1 = __float_as_uint(Bs[(kk + 4 + lr) * GBP + col]);
                MMA_TF32(c[0][nt], a[0][0], a[0][1], a[0][2], a[0][3], b0, b1);
                MMA_TF32(c[1][nt], a[1][0], a[1][1], a[1][2], a[1][3], b0, b1);
            }
        }
    }

    #pragma unroll
    for (int mt = 0; mt < 2; mt++) {
        int row = m0 + wm * 32 + mt * 16 + lq;
        #pragma unroll
        for (int nt = 0; nt < 8; nt++) {
            int col = wn * 64 + nt * 8 + 2 * lr;
            *(float2*)(outp + (size_t)row * DK + col) =
                make_float2(c[mt][nt][0], c[mt][nt][1]);
            *(float2*)(outp + (size_t)(row + 8) * DK + col) =
                make_float2(c[mt][nt][2], c[mt][nt][3]);
        }
    }
}

// ===========================================================================
// Flash attention (causal, online softmax), tf32 mma.
// grid (32, 16), 256 threads = 8 warps (4m x 2n).
// S: warp tile 16x32 over 64x64.  PV: warp tile 16x64 over 64x128.
// ===========================================================================
#define BM 64
#define BN 64
#define QP 132    // 132 mod 32 = 4 -> 4*lq + lr conflict-free (A / K-as-B frags)
#define KP 132
#define VP 136    // 136 mod 32 = 8 -> 8*lr + lq conflict-free (V-as-B frags)
#define SP 68     // 68 mod 32 = 4

struct __align__(16) AttnSmem {
    float Qs[BM * QP];
    float Ks[BN * KP];
    float Vs[BN * VP];
    float Ss[BM * SP];
    float mrow[BM];
    float lrow[BM];
    float crow[BM];
};
extern __shared__ char attn_raw[];

__global__ void __launch_bounds__(256) attn_kernel(float* __restrict__ out)
{
    AttnSmem& sm = *reinterpret_cast<AttnSmem*>(attn_raw);
    const int t = threadIdx.x;
    const int lane = t & 31, wid = t >> 5;
    const int wm = wid >> 1, wn = wid & 1;
    const int lq = lane >> 2, lr = lane & 3;
    const int b = blockIdx.y;
    const int qb = (int)(gridDim.x - 1) - (int)blockIdx.x;  // long CTAs first
    const int q0 = qb * BM;

    const float* Q = g_qkv[0] + (size_t)b * T * DK;
    const float* K = g_qkv[1] + (size_t)b * T * DK;
    const float* V = g_qkv[2] + (size_t)b * T * DK;

    #pragma unroll
    for (int i = 0; i < 8; i++) {
        int f = t + 256 * i;
        int r = f >> 5, cc = (f & 31) * 4;
        float4 qv = *(const float4*)(Q + (size_t)(q0 + r) * DK + cc);
        float* qp = &sm.Qs[r * QP + cc];
        qp[0] = f2tff(qv.x); qp[1] = f2tff(qv.y);
        qp[2] = f2tff(qv.z); qp[3] = f2tff(qv.w);
    }
    if (t < BM) { sm.mrow[t] = -1e30f; sm.lrow[t] = 0.0f; }

    float of[8][4];
    #pragma unroll
    for (int nt = 0; nt < 8; nt++)
        #pragma unroll
        for (int k = 0; k < 4; k++) of[nt][k] = 0.0f;

    const float scale = 0.08838834764831845f;  // 1/sqrt(128)

    for (int kb = 0; kb <= qb; kb++) {
        const int k0 = kb * BN;

        __syncthreads();
        #pragma unroll
        for (int i = 0; i < 8; i++) {
            int f = t + 256 * i;
            int r = f >> 5, cc = (f & 31) * 4;
            float4 kv = *(const float4*)(K + (size_t)(k0 + r) * DK + cc);
            float4 vv = *(const float4*)(V + (size_t)(k0 + r) * DK + cc);
            float* kp = &sm.Ks[r * KP + cc];
            kp[0] = f2tff(kv.x); kp[1] = f2tff(kv.y);
            kp[2] = f2tff(kv.z); kp[3] = f2tff(kv.w);
            float* vp = &sm.Vs[r * VP + cc];
            vp[0] = f2tff(vv.x); vp[1] = f2tff(vv.y);
            vp[2] = f2tff(vv.z); vp[3] = f2tff(vv.w);
        }
        __syncthreads();

        // ---- S = Q K^T ----
        float sc[4][4];
        #pragma unroll
        for (int nt = 0; nt < 4; nt++)
            #pragma unroll
            for (int k = 0; k < 4; k++) sc[nt][k] = 0.0f;

        #pragma unroll
        for (int kk = 0; kk < DK; kk += 8) {
            int r = 16 * wm + lq;
            unsigned a0 = __float_as_uint(sm.Qs[r * QP + kk + lr]);
            unsigned a1 = __float_as_uint(sm.Qs[(r + 8) * QP + kk + lr]);
            unsigned a2 = __float_as_uint(sm.Qs[r * QP + kk + 4 + lr]);
            unsigned a3 = __float_as_uint(sm.Qs[(r + 8) * QP + kk + 4 + lr]);
            #pragma unroll
            for (int nt = 0; nt < 4; nt++) {
                int n = 32 * wn + nt * 8 + lq;
                unsigned b0 = __float_as_uint(sm.Ks[n * KP + kk + lr]);
                unsigned b1 = __float_as_uint(sm.Ks[n * KP + kk + 4 + lr]);
                MMA_TF32(sc[nt], a0, a1, a2, a3, b0, b1);
            }
        }

        // ---- scale + causal mask (diag block only), store to Ss ----
        {
            int r1 = 16 * wm + lq, r2 = r1 + 8;
            if (kb == qb) {
                #pragma unroll
                for (int nt = 0; nt < 4; nt++) {
                    int cb = 32 * wn + nt * 8 + 2 * lr;
                    sm.Ss[r1 * SP + cb]     = (cb     <= r1) ? sc[nt][0] * scale : -1e30f;
                    sm.Ss[r1 * SP + cb + 1] = (cb + 1 <= r1) ? sc[nt][1] * scale : -1e30f;
                    sm.Ss[r2 * SP + cb]     = (cb     <= r2) ? sc[nt][2] * scale : -1e30f;
                    sm.Ss[r2 * SP + cb + 1] = (cb + 1 <= r2) ? sc[nt][3] * scale : -1e30f;
                }
            } else {
                #pragma unroll
                for (int nt = 0; nt < 4; nt++) {
                    int cb = 32 * wn + nt * 8 + 2 * lr;
                    sm.Ss[r1 * SP + cb]     = sc[nt][0] * scale;
                    sm.Ss[r1 * SP + cb + 1] = sc[nt][1] * scale;
                    sm.Ss[r2 * SP + cb]     = sc[nt][2] * scale;
                    sm.Ss[r2 * SP + cb + 1] = sc[nt][3] * scale;
                }
            }
        }
        __syncthreads();

        // ---- online softmax: 4 threads/row; P written tf32-rounded ----
        {
            int rr = t >> 2, pp = t & 3;
            float* srow = &sm.Ss[rr * SP + (pp << 4)];
            float mx = -1e30f;
            #pragma unroll
            for (int cc = 0; cc < 16; cc++) mx = fmaxf(mx, srow[cc]);
            mx = fmaxf(mx, __shfl_xor_sync(0xffffffffu, mx, 1));
            mx = fmaxf(mx, __shfl_xor_sync(0xffffffffu, mx, 2));
            float mold = sm.mrow[rr];
            float mnew = fmaxf(mold, mx);
            float sum = 0.0f;
            #pragma unroll
            for (int cc = 0; cc < 16; cc++) {
                float e = __expf(srow[cc] - mnew);
                srow[cc] = f2tff(e);
                sum += e;
            }
            sum += __shfl_xor_sync(0xffffffffu, sum, 1);
            sum += __shfl_xor_sync(0xffffffffu, sum, 2);
            if (pp == 0) {
                float corr = __expf(mold - mnew);
                sm.crow[rr] = corr;
                sm.lrow[rr] = sm.lrow[rr] * corr + sum;
                sm.mrow[rr] = mnew;
            }
        }
        __syncthreads();

        // ---- rescale O, then O += P V ----
        {
            int r1 = 16 * wm + lq;
            float c1 = sm.crow[r1], c2 = sm.crow[r1 + 8];
            #pragma unroll
            for (int nt = 0; nt < 8; nt++) {
                of[nt][0] *= c1; of[nt][1] *= c1;
                of[nt][2] *= c2; of[nt][3] *= c2;
            }
        }
        #pragma unroll
        for (int kk = 0; kk < BN; kk += 8) {
            int r = 16 * wm + lq;
            unsigned a0 = __float_as_uint(sm.Ss[r * SP + kk + lr]);
            unsigned a1 = __float_as_uint(sm.Ss[(r + 8) * SP + kk + lr]);
            unsigned a2 = __float_as_uint(sm.Ss[r * SP + kk + 4 + lr]);
            unsigned a3 = __float_as_uint(sm.Ss[(r + 8) * SP + kk + 4 + lr]);
            #pragma unroll
            for (int nt = 0; nt < 8; nt++) {
                int n = 64 * wn + nt * 8 + lq;
                unsigned b0 = __float_as_uint(sm.Vs[(kk + lr) * VP + n]);
                unsigned b1 = __float_as_uint(sm.Vs[(kk + 4 + lr) * VP + n]);
                MMA_TF32(of[nt], a0, a1, a2, a3, b0, b1);
            }
        }
    }

    // ---- epilogue: normalize and store ----
    {
        int r1 = 16 * wm + lq;
        float inv1 = 1.0f / sm.lrow[r1];
        float inv2 = 1.0f / sm.lrow[r1 + 8];
        float* op = out + ((size_t)b * T + q0) * DK;
        #pragma unroll
        for (int nt = 0; nt < 8; nt++) {
            int col = 64 * wn + nt * 8 + 2 * lr;
            *(float2*)(op + (size_t)r1 * DK + col) =
                make_float2(of[nt][0] * inv1, of[nt][1] * inv1);
            *(float2*)(op + (size_t)(r1 + 8) * DK + col) =
                make_float2(of[nt][2] * inv2, of[nt][3] * inv2);
        }
    }
}

// ===========================================================================
extern "C" void kernel_launch(void* const* d_in, const int* in_sizes, int n_in,
                              void* d_out, int out_size)
{
    const float* x  = (const float*)d_in[0];
    const float* Wq = (const float*)d_in[1];
    const float* Wk = (const float*)d_in[2];
    const float* Wv = (const float*)d_in[3];
    float* out = (float*)d_out;

    dim3 g1(3, BT / 128);
    qkv_gemm_kernel<<<g1, 256>>>(x, Wq, Wk, Wv);

    int smem = (int)sizeof(AttnSmem);
    cudaFuncSetAttribute(attn_kernel, cudaFuncAttributeMaxDynamicSharedMemorySize, smem);
    dim3 g2(T / BM, NB);
    attn_kernel<<<g2, 256, (size_t)smem>>>(out);
}

// round 3
// speedup vs baseline: 2.8186x; 1.1108x over previous
#include <cuda_runtime.h>

// SelfAttentionHead via tf32 mma.sync, register softmax, fragment-major smem.
// B=16, T=2048, DM=1024, DK=128, fp32 in/out.

#define NB 16
#define T 2048
#define DM 1024
#define DK 128
#define BT (NB * T)

__device__ float g_qkv[3][(size_t)BT * DK];

__device__ __forceinline__ unsigned f2tf(float f) {
    unsigned u; asm("cvt.rna.tf32.f32 %0, %1;" : "=r"(u) : "f"(f)); return u;
}
__device__ __forceinline__ float f2tff(float f) { return __uint_as_float(f2tf(f)); }

#define MMA_TF32(d, a0, a1, a2, a3, b0, b1)                                  \
    asm volatile("mma.sync.aligned.m16n8k8.row.col.f32.tf32.tf32.f32 "       \
                 "{%0,%1,%2,%3}, {%4,%5,%6,%7}, {%8,%9}, {%0,%1,%2,%3};"     \
                 : "+f"(d[0]), "+f"(d[1]), "+f"(d[2]), "+f"(d[3])            \
                 : "r"(a0), "r"(a1), "r"(a2), "r"(a3), "r"(b0), "r"(b1))

// ===========================================================================
// QKV GEMM (unchanged from R2): out[sel] = x @ W_sel. M=32768, K=1024, N=128.
// ===========================================================================
#define KC 16
#define GAP 20
#define GBP 136

__global__ void __launch_bounds__(256) qkv_gemm_kernel(
    const float* __restrict__ x, const float* __restrict__ Wq,
    const float* __restrict__ Wk, const float* __restrict__ Wv)
{
    __shared__ float As[128 * GAP];
    __shared__ float Bs[KC * GBP];

    const int sel = blockIdx.x;
    const float* W = (sel == 0) ? Wq : (sel == 1 ? Wk : Wv);
    float* outp = g_qkv[sel];
    const int m0 = blockIdx.y * 128;

    const int t = threadIdx.x;
    const int lane = t & 31, wid = t >> 5;
    const int wm = wid >> 1, wn = wid & 1;
    const int lq = lane >> 2, lr = lane & 3;

    const float* xp = x + (size_t)m0 * DM;

    float4 ra[2], rb[2];
    #pragma unroll
    for (int i = 0; i < 2; i++) {
        int f = t + 256 * i;
        ra[i] = *(const float4*)(xp + (size_t)(f >> 2) * DM + (f & 3) * 4);
        rb[i] = *(const float4*)(W + (size_t)(f >> 5) * DK + (f & 31) * 4);
    }

    float c[2][8][4];
    #pragma unroll
    for (int mt = 0; mt < 2; mt++)
        #pragma unroll
        for (int nt = 0; nt < 8; nt++)
            #pragma unroll
            for (int k = 0; k < 4; k++) c[mt][nt][k] = 0.0f;

    for (int k0 = 0; k0 < DM; k0 += KC) {
        __syncthreads();
        #pragma unroll
        for (int i = 0; i < 2; i++) {
            int f = t + 256 * i;
            float4 a = ra[i], bv = rb[i];
            float* ap = &As[(f >> 2) * GAP + (f & 3) * 4];
            ap[0] = f2tff(a.x); ap[1] = f2tff(a.y);
            ap[2] = f2tff(a.z); ap[3] = f2tff(a.w);
            float* bp = &Bs[(f >> 5) * GBP + (f & 31) * 4];
            bp[0] = f2tff(bv.x); bp[1] = f2tff(bv.y);
            bp[2] = f2tff(bv.z); bp[3] = f2tff(bv.w);
        }
        __syncthreads();

        if (k0 + KC < DM) {
            #pragma unroll
            for (int i = 0; i < 2; i++) {
                int f = t + 256 * i;
                ra[i] = *(const float4*)(xp + (size_t)(f >> 2) * DM + (k0 + KC) + (f & 3) * 4);
                rb[i] = *(const float4*)(W + (size_t)(k0 + KC + (f >> 5)) * DK + (f & 31) * 4);
            }
        }

        #pragma unroll
        for (int kk = 0; kk < KC; kk += 8) {
            unsigned a[2][4];
            #pragma unroll
            for (int mt = 0; mt < 2; mt++) {
                int r = wm * 32 + mt * 16 + lq;
                a[mt][0] = __float_as_uint(As[r * GAP + kk + lr]);
                a[mt][1] = __float_as_uint(As[(r + 8) * GAP + kk + lr]);
                a[mt][2] = __float_as_uint(As[r * GAP + kk + 4 + lr]);
                a[mt][3] = __float_as_uint(As[(r + 8) * GAP + kk + 4 + lr]);
            }
            #pragma unroll
            for (int nt = 0; nt < 8; nt++) {
                int col = wn * 64 + nt * 8 + lq;
                unsigned b0 = __float_as_uint(Bs[(kk + lr) * GBP + col]);
                unsigned b1 = __float_as_uint(Bs[(kk + 4 + lr) * GBP + col]);
                MMA_TF32(c[0][nt], a[0][0], a[0][1], a[0][2], a[0][3], b0, b1);
                MMA_TF32(c[1][nt], a[1][0], a[1][1], a[1][2], a[1][3], b0, b1);
            }
        }
    }

    #pragma unroll
    for (int mt = 0; mt < 2; mt++) {
        int row = m0 + wm * 32 + mt * 16 + lq;
        #pragma unroll
        for (int nt = 0; nt < 8; nt++) {
            int col = wn * 64 + nt * 8 + 2 * lr;
            *(float2*)(outp + (size_t)row * DK + col) =
                make_float2(c[mt][nt][0], c[mt][nt][1]);
            *(float2*)(outp + (size_t)(row + 8) * DK + col) =
                make_float2(c[mt][nt][2], c[mt][nt][3]);
        }
    }
}

// ===========================================================================
// Flash attention: register softmax + partial-O per wn-warp + frag-major smem.
// grid (32, 16), 256 threads = 8 warps: wm = wid>>1 (row group), wn = wid&1
// (key-column half). Warp S tile: rows [16wm,16wm+16) x cols [32wn,32wn+32).
// O partial per warp: 16 rows x 128 cols (summed across wn pair in epilogue).
// ===========================================================================
#define BM 64
#define BN 64
#define QFP 132   // pitch per (rg,kkc) frag row: 4*lq+lr LDS.128 conflict-free
#define KFP 66    // pitch per frag row for K/V float2 frags

struct __align__(16) AttnSmem {
    float Qf[64 * QFP];    // [rg*16+kkc][lane*4+slot]
    float Kf[128 * KFP];   // [ng*16+kkc][lane*2+slot]
    float Vf[128 * KFP];   // [kkc*16+ng][lane*2+slot]
    float pmax[128];       // [wn*64+row]
    float psum[128];
};
extern __shared__ char attn_raw[];

__global__ void __launch_bounds__(256, 2) attn_kernel(float* __restrict__ out)
{
    AttnSmem& sm = *reinterpret_cast<AttnSmem*>(attn_raw);
    const int t = threadIdx.x;
    const int lane = t & 31, wid = t >> 5;
    const int wm = wid >> 1, wn = wid & 1;
    const int lq = lane >> 2, lr = lane & 3;
    const int b = blockIdx.y;
    const int qb = (int)(gridDim.x - 1) - (int)blockIdx.x;  // long CTAs first
    const int q0 = qb * BM;

    const float* Q = g_qkv[0] + (size_t)b * T * DK;
    const float* K = g_qkv[1] + (size_t)b * T * DK;
    const float* V = g_qkv[2] + (size_t)b * T * DK;

    // ---- Q -> fragment-major smem (once) ----
    #pragma unroll
    for (int i = 0; i < 8; i++) {
        int f = t + 256 * i;
        int r = f >> 5, c4 = f & 31;
        float4 qv = *(const float4*)(Q + (size_t)(q0 + r) * DK + 4 * c4);
        int rg = r >> 4, lqq = r & 7, half = (r >> 3) & 1;
        int kkc = c4 >> 1, khalf = c4 & 1;
        float* qp = &sm.Qf[(rg * 16 + kkc) * QFP + half + 2 * khalf];
        qp[(lqq * 4 + 0) * 4] = f2tff(qv.x);
        qp[(lqq * 4 + 1) * 4] = f2tff(qv.y);
        qp[(lqq * 4 + 2) * 4] = f2tff(qv.z);
        qp[(lqq * 4 + 3) * 4] = f2tff(qv.w);
    }

    const int r1 = 16 * wm + lq;     // this thread's two S rows
    // row state (duplicated across the 8 threads sharing each row)
    float m1 = -1e30f, m2 = -1e30f;
    float l1 = 0.0f, l2 = 0.0f;
    float pc1 = 1.0f, pc2 = 1.0f;

    float o[16][4];
    #pragma unroll
    for (int ng = 0; ng < 16; ng++)
        #pragma unroll
        for (int k = 0; k < 4; k++) o[ng][k] = 0.0f;

    const float scale = 0.08838834764831845f;  // 1/sqrt(128)

    const float* qbase = &sm.Qf[(wm * 16) * QFP + lane * 4];
    const float* kbase = &sm.Kf[(wn * 4 * 16) * KFP + lane * 2];
    const float* vbase = &sm.Vf[(wn * 4 * 16) * KFP + lane * 2];

    for (int kb = 0; kb <= qb; kb++) {
        const int k0 = kb * BN;

        __syncthreads();   // syncA: prev PV reads done; prev psum visible
        if (kb > 0) {
            l1 = l1 * pc1 + sm.psum[r1] + sm.psum[64 + r1];
            l2 = l2 * pc2 + sm.psum[r1 + 8] + sm.psum[64 + r1 + 8];
        }

        // ---- K, V -> fragment-major smem ----
        #pragma unroll
        for (int i = 0; i < 8; i++) {
            int f = t + 256 * i;
            int r = f >> 5, c4 = f & 31;
            float4 kv = *(const float4*)(K + (size_t)(k0 + r) * DK + 4 * c4);
            float4 vv = *(const float4*)(V + (size_t)(k0 + r) * DK + 4 * c4);
            // K frag store
            {
                int ng = r >> 3, lqq = r & 7, kkc = c4 >> 1, s = c4 & 1;
                float* kp = &sm.Kf[(ng * 16 + kkc) * KFP + s];
                kp[(lqq * 4 + 0) * 2] = f2tff(kv.x);
                kp[(lqq * 4 + 1) * 2] = f2tff(kv.y);
                kp[(lqq * 4 + 2) * 2] = f2tff(kv.z);
                kp[(lqq * 4 + 3) * 2] = f2tff(kv.w);
            }
            // V frag store
            {
                int kkc = r >> 3, lrr = r & 3, s = (r >> 2) & 1;
                int ng = c4 >> 1, lq0 = 4 * (c4 & 1);
                float* vp = &sm.Vf[(kkc * 16 + ng) * KFP + lrr * 2 + s];
                vp[(lq0 + 0) * 8] = f2tff(vv.x);
                vp[(lq0 + 1) * 8] = f2tff(vv.y);
                vp[(lq0 + 2) * 8] = f2tff(vv.z);
                vp[(lq0 + 3) * 8] = f2tff(vv.w);
            }
        }
        __syncthreads();   // syncB: KV visible

        // ---- S = Q K^T : warp 16x32 tile in registers ----
        float sc[4][4];
        #pragma unroll
        for (int nt = 0; nt < 4; nt++)
            #pragma unroll
            for (int k = 0; k < 4; k++) sc[nt][k] = 0.0f;

        #pragma unroll
        for (int kkc = 0; kkc < 16; kkc++) {
            float4 A = *(const float4*)(qbase + kkc * QFP);
            unsigned a0 = __float_as_uint(A.x), a1 = __float_as_uint(A.y);
            unsigned a2 = __float_as_uint(A.z), a3 = __float_as_uint(A.w);
            #pragma unroll
            for (int nt = 0; nt < 4; nt++) {
                float2 Bv = *(const float2*)(kbase + (nt * 16 + kkc) * KFP);
                MMA_TF32(sc[nt], a0, a1, a2, a3,
                         __float_as_uint(Bv.x), __float_as_uint(Bv.y));
            }
        }

        // ---- scale + causal mask (diag block only) ----
        if (kb == qb) {
            #pragma unroll
            for (int nt = 0; nt < 4; nt++) {
                int cb = 32 * wn + nt * 8 + 2 * lr;
                sc[nt][0] = (cb     <= r1)     ? sc[nt][0] * scale : -1e30f;
                sc[nt][1] = (cb + 1 <= r1)     ? sc[nt][1] * scale : -1e30f;
                sc[nt][2] = (cb     <= r1 + 8) ? sc[nt][2] * scale : -1e30f;
                sc[nt][3] = (cb + 1 <= r1 + 8) ? sc[nt][3] * scale : -1e30f;
            }
        } else {
            #pragma unroll
            for (int nt = 0; nt < 4; nt++)
                #pragma unroll
                for (int k = 0; k < 4; k++) sc[nt][k] *= scale;
        }

        // ---- warp-partial row max (quad shfl) ----
        float mx1 = -1e30f, mx2 = -1e30f;
        #pragma unroll
        for (int nt = 0; nt < 4; nt++) {
            mx1 = fmaxf(mx1, fmaxf(sc[nt][0], sc[nt][1]));
            mx2 = fmaxf(mx2, fmaxf(sc[nt][2], sc[nt][3]));
        }
        mx1 = fmaxf(mx1, __shfl_xor_sync(0xffffffffu, mx1, 1));
        mx1 = fmaxf(mx1, __shfl_xor_sync(0xffffffffu, mx1, 2));
        mx2 = fmaxf(mx2, __shfl_xor_sync(0xffffffffu, mx2, 1));
        mx2 = fmaxf(mx2, __shfl_xor_sync(0xffffffffu, mx2, 2));
        if (lr == 0) {
            sm.pmax[wn * 64 + r1]     = mx1;
            sm.pmax[wn * 64 + r1 + 8] = mx2;
        }
        __syncthreads();   // syncC

        // ---- combine partials, update m, compute corr ----
        {
            float om1 = fmaxf(sm.pmax[r1], sm.pmax[64 + r1]);
            float om2 = fmaxf(sm.pmax[r1 + 8], sm.pmax[64 + r1 + 8]);
            float mn1 = fmaxf(m1, om1);
            float mn2 = fmaxf(m2, om2);
            pc1 = __expf(m1 - mn1);
            pc2 = __expf(m2 - mn2);
            m1 = mn1; m2 = mn2;
        }

        // ---- exp + warp-partial sum ----
        float s1 = 0.0f, s2 = 0.0f;
        #pragma unroll
        for (int nt = 0; nt < 4; nt++) {
            sc[nt][0] = __expf(sc[nt][0] - m1);
            sc[nt][1] = __expf(sc[nt][1] - m1);
            sc[nt][2] = __expf(sc[nt][2] - m2);
            sc[nt][3] = __expf(sc[nt][3] - m2);
            s1 += sc[nt][0] + sc[nt][1];
            s2 += sc[nt][2] + sc[nt][3];
        }
        s1 += __shfl_xor_sync(0xffffffffu, s1, 1);
        s1 += __shfl_xor_sync(0xffffffffu, s1, 2);
        s2 += __shfl_xor_sync(0xffffffffu, s2, 1);
        s2 += __shfl_xor_sync(0xffffffffu, s2, 2);
        if (lr == 0) {
            sm.psum[wn * 64 + r1]     = s1;
            sm.psum[wn * 64 + r1 + 8] = s2;
        }

        // ---- rescale partial O ----
        #pragma unroll
        for (int ng = 0; ng < 16; ng++) {
            o[ng][0] *= pc1; o[ng][1] *= pc1;
            o[ng][2] *= pc2; o[ng][3] *= pc2;
        }

        // ---- PV: P (regs, shfl-remapped) x V (frag smem) ----
        const int src1 = (lane & ~3) | (lr >> 1);
        const int src2 = src1 + 2;
        const bool odd = (lr & 1);
        #pragma unroll
        for (int c = 0; c < 4; c++) {
            float p0 = __shfl_sync(0xffffffffu, sc[c][0], src1);
            float p1 = __shfl_sync(0xffffffffu, sc[c][1], src1);
            float p2 = __shfl_sync(0xffffffffu, sc[c][2], src1);
            float p3 = __shfl_sync(0xffffffffu, sc[c][3], src1);
            float u0 = __shfl_sync(0xffffffffu, sc[c][0], src2);
            float u1 = __shfl_sync(0xffffffffu, sc[c][1], src2);
            float u2 = __shfl_sync(0xffffffffu, sc[c][2], src2);
            float u3 = __shfl_sync(0xffffffffu, sc[c][3], src2);
            unsigned a0 = f2tf(odd ? p1 : p0);
            unsigned a1 = f2tf(odd ? p3 : p2);
            unsigned a2 = f2tf(odd ? u1 : u0);
            unsigned a3 = f2tf(odd ? u3 : u2);
            const float* vb = vbase + (c * 16) * KFP;
            #pragma unroll
            for (int ng = 0; ng < 16; ng++) {
                float2 Bv = *(const float2*)(vb + ng * KFP);
                MMA_TF32(o[ng], a0, a1, a2, a3,
                         __float_as_uint(Bv.x), __float_as_uint(Bv.y));
            }
        }
    }

    // ---- final l update ----
    __syncthreads();
    l1 = l1 * pc1 + sm.psum[r1] + sm.psum[64 + r1];
    l2 = l2 * pc2 + sm.psum[r1 + 8] + sm.psum[64 + r1 + 8];

    // ---- combine wn partials: wn=1 dumps to smem, wn=0 adds + stores ----
    float* buf = sm.Kf;   // reuse (needs 64*132 floats; Kf+Vf has room)
    if (wn == 1) {
        #pragma unroll
        for (int ng = 0; ng < 16; ng++) {
            int cb = ng * 8 + 2 * lr;
            buf[(wm * 16 + lq) * 132 + cb]     = o[ng][0];
            buf[(wm * 16 + lq) * 132 + cb + 1] = o[ng][1];
            buf[(wm * 16 + lq + 8) * 132 + cb]     = o[ng][2];
            buf[(wm * 16 + lq + 8) * 132 + cb + 1] = o[ng][3];
        }
    }
    __syncthreads();
    if (wn == 0) {
        float inv1 = 1.0f / l1;
        float inv2 = 1.0f / l2;
        float* op = out + ((size_t)b * T + q0) * DK;
        #pragma unroll
        for (int ng = 0; ng < 16; ng++) {
            int cb = ng * 8 + 2 * lr;
            float v00 = (o[ng][0] + buf[(wm * 16 + lq) * 132 + cb])     * inv1;
            float v01 = (o[ng][1] + buf[(wm * 16 + lq) * 132 + cb + 1]) * inv1;
            float v10 = (o[ng][2] + buf[(wm * 16 + lq + 8) * 132 + cb])     * inv2;
            float v11 = (o[ng][3] + buf[(wm * 16 + lq + 8) * 132 + cb + 1]) * inv2;
            *(float2*)(op + (size_t)r1 * DK + cb)       = make_float2(v00, v01);
            *(float2*)(op + (size_t)(r1 + 8) * DK + cb) = make_float2(v10, v11);
        }
    }
}

// ===========================================================================
extern "C" void kernel_launch(void* const* d_in, const int* in_sizes, int n_in,
                              void* d_out, int out_size)
{
    const float* x  = (const float*)d_in[0];
    const float* Wq = (const float*)d_in[1];
    const float* Wk = (const float*)d_in[2];
    const float* Wv = (const float*)d_in[3];
    float* out = (float*)d_out;

    dim3 g1(3, BT / 128);
    qkv_gemm_kernel<<<g1, 256>>>(x, Wq, Wk, Wv);

    int smem = (int)sizeof(AttnSmem);
    cudaFuncSetAttribute(attn_kernel, cudaFuncAttributeMaxDynamicSharedMemorySize, smem);
    dim3 g2(T / BM, NB);
    attn_kernel<<<g2, 256, (size_t)smem>>>(out);
}